// round 3
// baseline (speedup 1.0000x reference)
#include <cuda_runtime.h>

#define N_NODES 100000
#define N_EDGES 3200000
#define N_FEAT  512
#define HID     16
#define N_CLS   64

// ---------------- scratch (device globals; no allocation allowed) ----------
__device__ float g_h1[N_NODES * HID];     // hidden activations (layer1 out / relu)
__device__ float g_agg[N_NODES * HID];    // aggregation buffer (reused both layers)
__device__ float g_dinv[N_NODES];         // deg -> rsqrt(deg)
__device__ float g_norm[N_EDGES];         // per-edge symmetric norm
__device__ int   g_src[N_EDGES];
__device__ int   g_dst[N_EDGES];
__device__ int   g_is64;

// ---------------- dtype detection: int64 vs int32 edge_index ---------------
__global__ void k_detect(const unsigned* __restrict__ words) {
    unsigned any = 0;
    for (int i = threadIdx.x; i < 4096; i += blockDim.x) any |= words[2 * i + 1];
    int r = __syncthreads_or((int)(any != 0));
    if (threadIdx.x == 0) g_is64 = (r == 0);  // all-high-words-zero => int64
}

// ---------------- degree init (1.0 accounts for self-loop) -----------------
__global__ void k_deg_init() {
    int i = blockIdx.x * blockDim.x + threadIdx.x;
    if (i < N_NODES) g_dinv[i] = 1.0f;
}

// ---------------- edge conversion + degree accumulation --------------------
__global__ void k_prep(const void* __restrict__ eidx, int E) {
    int e = blockIdx.x * blockDim.x + threadIdx.x;
    if (e >= E) return;
    int s, d;
    if (g_is64) {
        const long long* p = (const long long*)eidx;
        s = (int)p[e]; d = (int)p[E + e];
    } else {
        const int* p = (const int*)eidx;
        s = p[e]; d = p[E + e];
    }
    g_src[e] = s;
    g_dst[e] = d;
    atomicAdd(&g_dinv[d], 1.0f);
}

__global__ void k_rsqrt() {
    int i = blockIdx.x * blockDim.x + threadIdx.x;
    if (i < N_NODES) g_dinv[i] = rsqrtf(g_dinv[i]);   // deg >= 1 always
}

__global__ void k_norm(int E) {
    int e = blockIdx.x * blockDim.x + threadIdx.x;
    if (e >= E) return;
    g_norm[e] = g_dinv[g_src[e]] * g_dinv[g_dst[e]];
}

// ---------------- GEMM1: h1 = x @ W1  (100000x512 @ 512x16) ----------------
// 256 threads = 8 warps; each warp computes 4 nodes; W1^T staged in smem.
__global__ __launch_bounds__(256) void k_gemm1(const float* __restrict__ x,
                                               const float* __restrict__ W1) {
    __shared__ float Ws[HID * N_FEAT];   // Ws[j*512 + k] = W1[k*16 + j], 32 KB
    for (int idx = threadIdx.x; idx < N_FEAT * HID; idx += blockDim.x)
        Ws[(idx & 15) * N_FEAT + (idx >> 4)] = W1[idx];
    __syncthreads();

    int lane  = threadIdx.x & 31;
    int warp  = threadIdx.x >> 5;
    int nbase = blockIdx.x * 32 + warp * 4;   // 3125 blocks * 32 nodes = 100000

    float acc[4][16];
#pragma unroll
    for (int c = 0; c < 4; c++)
#pragma unroll
        for (int j = 0; j < 16; j++) acc[c][j] = 0.0f;

    const float* xb = x + (size_t)nbase * N_FEAT;
#pragma unroll 4
    for (int k0 = 0; k0 < N_FEAT; k0 += 32) {
        int k = k0 + lane;
        float x0 = xb[k];
        float x1 = xb[N_FEAT + k];
        float x2 = xb[2 * N_FEAT + k];
        float x3 = xb[3 * N_FEAT + k];
#pragma unroll
        for (int j = 0; j < 16; j++) {
            float w = Ws[j * N_FEAT + k];
            acc[0][j] += x0 * w;
            acc[1][j] += x1 * w;
            acc[2][j] += x2 * w;
            acc[3][j] += x3 * w;
        }
    }

#pragma unroll
    for (int c = 0; c < 4; c++) {
        float res = 0.0f;
#pragma unroll
        for (int j = 0; j < 16; j++) {
            float v = acc[c][j];
            v += __shfl_xor_sync(0xffffffffu, v, 16);
            v += __shfl_xor_sync(0xffffffffu, v, 8);
            v += __shfl_xor_sync(0xffffffffu, v, 4);
            v += __shfl_xor_sync(0xffffffffu, v, 2);
            v += __shfl_xor_sync(0xffffffffu, v, 1);
            if (lane == j) res = v;
        }
        if (lane < 16) g_h1[(nbase + c) * HID + lane] = res;
    }
}

// ---------------- zero aggregation buffer ----------------------------------
__global__ void k_zero_agg() {
    int i = blockIdx.x * blockDim.x + threadIdx.x;
    if (i < N_NODES * HID / 4) ((float4*)g_agg)[i] = make_float4(0.f, 0.f, 0.f, 0.f);
}

// ---------------- edge scatter: agg[dst] += g_h1[src] * norm ---------------
// 4 threads per edge; each does one 16B gather + one red.global.add.v4.f32.
// NOTE: g_h1 referenced from DEVICE code (host-side symbol pass is invalid and
// silently reads the host shadow via ATS on GB300 — the round-1 bug).
__global__ void k_scatter(int E) {
    int t = blockIdx.x * blockDim.x + threadIdx.x;
    if (t >= E * 4) return;
    int e = t >> 2, c = t & 3;
    int s = g_src[e], d = g_dst[e];
    float nm = g_norm[e];
    float4 v = __ldg((const float4*)(g_h1 + s * HID) + c);
    v.x *= nm; v.y *= nm; v.z *= nm; v.w *= nm;
    float* ap = &g_agg[d * HID + c * 4];
    asm volatile("red.global.add.v4.f32 [%0], {%1,%2,%3,%4};"
                 :: "l"(ap), "f"(v.x), "f"(v.y), "f"(v.z), "f"(v.w)
                 : "memory");
}

// ---------------- post layer1: h = relu(agg + b1 + selfloop) ---------------
__global__ void k_post1(const float* __restrict__ b1) {
    int idx = blockIdx.x * blockDim.x + threadIdx.x;
    if (idx >= N_NODES * HID) return;
    int n = idx >> 4, j = idx & 15;
    float dv = g_dinv[n];
    float v = g_agg[idx] + b1[j] + g_h1[idx] * dv * dv;
    g_h1[idx] = fmaxf(v, 0.0f);
}

// ---------------- final: (agg2 + selfloop) @ W2 + b2 -> log_softmax --------
// one warp per node; lanes hold 2 of 64 classes each.
__global__ __launch_bounds__(256) void k_final(const float* __restrict__ W2,
                                               const float* __restrict__ b2,
                                               float* __restrict__ out) {
    __shared__ float W2s[HID * N_CLS];   // [j][c] row-major, 4 KB
    __shared__ float b2s[N_CLS];
    for (int i = threadIdx.x; i < HID * N_CLS; i += blockDim.x) W2s[i] = W2[i];
    for (int i = threadIdx.x; i < N_CLS; i += blockDim.x) b2s[i] = b2[i];
    __syncthreads();

    int gw   = (blockIdx.x * blockDim.x + threadIdx.x) >> 5;
    int lane = threadIdx.x & 31;
    if (gw >= N_NODES) return;
    int n = gw;

    float dv  = g_dinv[n];
    float dv2 = dv * dv;
    float tj  = 0.0f;
    if (lane < HID) tj = g_agg[n * HID + lane] + g_h1[n * HID + lane] * dv2;

    float z0 = b2s[lane], z1 = b2s[lane + 32];
#pragma unroll
    for (int j = 0; j < HID; j++) {
        float t = __shfl_sync(0xffffffffu, tj, j);
        z0 += t * W2s[j * N_CLS + lane];
        z1 += t * W2s[j * N_CLS + lane + 32];
    }

    float m = fmaxf(z0, z1);
#pragma unroll
    for (int off = 16; off > 0; off >>= 1)
        m = fmaxf(m, __shfl_xor_sync(0xffffffffu, m, off));
    float s = __expf(z0 - m) + __expf(z1 - m);
#pragma unroll
    for (int off = 16; off > 0; off >>= 1)
        s += __shfl_xor_sync(0xffffffffu, s, off);
    float l = m + __logf(s);

    out[n * N_CLS + lane]      = z0 - l;
    out[n * N_CLS + lane + 32] = z1 - l;
}

// ---------------- launch ---------------------------------------------------
extern "C" void kernel_launch(void* const* d_in, const int* in_sizes, int n_in,
                              void* d_out, int out_size) {
    const float* x    = (const float*)d_in[0];
    const void*  eidx = d_in[1];
    const float* W1   = (const float*)d_in[2];
    const float* b1   = (const float*)d_in[3];
    const float* W2   = (const float*)d_in[4];
    const float* b2   = (const float*)d_in[5];
    float* out = (float*)d_out;

    int E = in_sizes[1] / 2;
    if (E > N_EDGES) E = N_EDGES;

    const int T = 256;
    int nb_nodes = (N_NODES + T - 1) / T;
    int nb_edges = (E + T - 1) / T;
    int nb_scat  = (E * 4 + T - 1) / T;
    int nb_nh    = (N_NODES * HID + T - 1) / T;
    int nb_zero  = (N_NODES * HID / 4 + T - 1) / T;
    int nb_warp  = (N_NODES * 32 + T - 1) / T;

    k_detect<<<1, 256>>>((const unsigned*)eidx);
    k_deg_init<<<nb_nodes, T>>>();
    k_prep<<<nb_edges, T>>>(eidx, E);
    k_rsqrt<<<nb_nodes, T>>>();
    k_norm<<<nb_edges, T>>>(E);

    k_gemm1<<<N_NODES / 32, T>>>(x, W1);

    k_zero_agg<<<nb_zero, T>>>();
    k_scatter<<<nb_scat, T>>>(E);
    k_post1<<<nb_nh, T>>>(b1);

    k_zero_agg<<<nb_zero, T>>>();
    k_scatter<<<nb_scat, T>>>(E);

    k_final<<<nb_warp, T>>>(W2, b2, out);
}

// round 4
// speedup vs baseline: 1.2761x; 1.2761x over previous
#include <cuda_runtime.h>

#define N_NODES 100000
#define N_EDGES 3200000
#define N_FEAT  512
#define HID     16
#define N_CLS   64
#define NB_N    391              // ceil(N_NODES/256)

// ---------------- scratch (device globals) ---------------------------------
__device__ float g_h1[N_NODES * HID];    // x@W1, later layer-2 aggregation out
__device__ float g_h2[N_NODES * HID];    // layer-1 output (post relu)
__device__ float g_dinv[N_NODES];
__device__ int   g_cnt[N_NODES];         // in-degree histogram (excl self-loop)
__device__ int   g_row[N_NODES + 1];     // CSR row offsets
__device__ int   g_cursor[N_NODES];
__device__ int2  g_edge[N_EDGES];        // {src, __float_as_int(dinv[src])}, dst-sorted
__device__ int   g_src[N_EDGES];
__device__ int   g_dst[N_EDGES];
__device__ int   g_bsum[NB_N];
__device__ int   g_boff[NB_N];
__device__ int   g_is64;

// ---------------- init: zero histogram + detect int64 vs int32 -------------
__global__ void k_init(const unsigned* __restrict__ words) {
    int i = blockIdx.x * blockDim.x + threadIdx.x;
    if (i < N_NODES) g_cnt[i] = 0;
    if (blockIdx.x == 0) {
        unsigned any = 0;
        for (int k = threadIdx.x; k < 4096; k += blockDim.x) any |= words[2 * k + 1];
        int r = __syncthreads_or((int)(any != 0));
        if (threadIdx.x == 0) g_is64 = (r == 0);   // all-high-words zero => int64
    }
}

// ---------------- convert edges + degree histogram --------------------------
__global__ void k_prep(const void* __restrict__ eidx, int E) {
    int e = blockIdx.x * blockDim.x + threadIdx.x;
    if (e >= E) return;
    int s, d;
    if (g_is64) {
        const long long* p = (const long long*)eidx;
        s = (int)p[e]; d = (int)p[E + e];
    } else {
        const int* p = (const int*)eidx;
        s = p[e]; d = p[E + e];
    }
    g_src[e] = s;
    g_dst[e] = d;
    atomicAdd(&g_cnt[d], 1);
}

// ---------------- scan stage 1: per-block sums ------------------------------
__global__ void k_scan1() {
    int i = blockIdx.x * blockDim.x + threadIdx.x;
    int v = (i < N_NODES) ? g_cnt[i] : 0;
#pragma unroll
    for (int o = 16; o > 0; o >>= 1) v += __shfl_down_sync(0xffffffffu, v, o);
    __shared__ int ws[8];
    if ((threadIdx.x & 31) == 0) ws[threadIdx.x >> 5] = v;
    __syncthreads();
    if (threadIdx.x == 0) {
        int s = 0;
#pragma unroll
        for (int k = 0; k < 8; k++) s += ws[k];
        g_bsum[blockIdx.x] = s;
    }
}

// ---------------- scan stage 2: exclusive scan of block sums ----------------
__global__ void k_scan2() {
    __shared__ int sm[512];
    int t = threadIdx.x;
    int v = (t < NB_N) ? g_bsum[t] : 0;
    sm[t] = v;
    __syncthreads();
#pragma unroll
    for (int o = 1; o < 512; o <<= 1) {
        int y = (t >= o) ? sm[t - o] : 0;
        __syncthreads();
        sm[t] += y;
        __syncthreads();
    }
    if (t < NB_N) g_boff[t] = sm[t] - v;   // exclusive
}

// ---------------- scan stage 3: row offsets, cursors, dinv ------------------
__global__ void k_scan3() {
    int i = blockIdx.x * blockDim.x + threadIdx.x;
    int lane = threadIdx.x & 31, warp = threadIdx.x >> 5;
    int v = (i < N_NODES) ? g_cnt[i] : 0;
    int x = v;
#pragma unroll
    for (int o = 1; o < 32; o <<= 1) {
        int y = __shfl_up_sync(0xffffffffu, x, o);
        if (lane >= o) x += y;
    }
    __shared__ int ws[8];
    if (lane == 31) ws[warp] = x;
    __syncthreads();
    if (threadIdx.x == 0) {
        int s = 0;
#pragma unroll
        for (int k = 0; k < 8; k++) { int t = ws[k]; ws[k] = s; s += t; }
    }
    __syncthreads();
    int excl = x - v + ws[warp] + g_boff[blockIdx.x];
    if (i < N_NODES) {
        g_row[i]    = excl;
        g_cursor[i] = excl;
        g_dinv[i]   = rsqrtf((float)v + 1.0f);     // +1: self-loop
        if (i == N_NODES - 1) g_row[N_NODES] = excl + v;
    }
}

// ---------------- fill CSR: dst-sorted {src, dinv[src]} ---------------------
__global__ void k_fill(int E) {
    int e = blockIdx.x * blockDim.x + threadIdx.x;
    if (e >= E) return;
    int s = g_src[e], d = g_dst[e];
    int pos = atomicAdd(&g_cursor[d], 1);
    g_edge[pos] = make_int2(s, __float_as_int(g_dinv[s]));
}

// ---------------- GEMM1: h1 = x @ W1 with packed f32x2 FMA ------------------
// 8 warps/block, warp computes 4 nodes; W1^T staged as float2 pairs in SMEM.
__global__ __launch_bounds__(256) void k_gemm1(const float* __restrict__ x,
                                               const float* __restrict__ W1) {
    __shared__ float2 Ws2[8 * N_FEAT];   // Ws2[j2*512 + k] = (W1[k][2j2], W1[k][2j2+1])
    for (int idx = threadIdx.x; idx < 8 * N_FEAT; idx += blockDim.x) {
        int j2 = idx & 7, k = idx >> 3;
        Ws2[j2 * N_FEAT + k] = make_float2(W1[k * HID + 2 * j2], W1[k * HID + 2 * j2 + 1]);
    }
    __syncthreads();

    int lane  = threadIdx.x & 31;
    int warp  = threadIdx.x >> 5;
    int nbase = blockIdx.x * 32 + warp * 4;

    unsigned long long acc[4][8];
#pragma unroll
    for (int c = 0; c < 4; c++)
#pragma unroll
        for (int j = 0; j < 8; j++) acc[c][j] = 0ull;

    const float* xb = x + (size_t)nbase * N_FEAT;
    const unsigned long long* Wsu = (const unsigned long long*)Ws2;

#pragma unroll 2
    for (int k0 = 0; k0 < N_FEAT; k0 += 32) {
        int k = k0 + lane;
        float xv[4];
        xv[0] = xb[k];
        xv[1] = xb[N_FEAT + k];
        xv[2] = xb[2 * N_FEAT + k];
        xv[3] = xb[3 * N_FEAT + k];
        unsigned long long xx[4];
#pragma unroll
        for (int c = 0; c < 4; c++)
            asm("mov.b64 %0, {%1, %1};" : "=l"(xx[c]) : "f"(xv[c]));
#pragma unroll
        for (int j2 = 0; j2 < 8; j2++) {
            unsigned long long w = Wsu[j2 * N_FEAT + k];
#pragma unroll
            for (int c = 0; c < 4; c++)
                asm("fma.rn.f32x2 %0, %1, %2, %0;" : "+l"(acc[c][j2]) : "l"(xx[c]), "l"(w));
        }
    }

#pragma unroll
    for (int c = 0; c < 4; c++) {
        float av[16];
#pragma unroll
        for (int j2 = 0; j2 < 8; j2++)
            asm("mov.b64 {%0, %1}, %2;" : "=f"(av[2 * j2]), "=f"(av[2 * j2 + 1]) : "l"(acc[c][j2]));
        float res = 0.0f;
#pragma unroll
        for (int j = 0; j < 16; j++) {
            float v = av[j];
            v += __shfl_xor_sync(0xffffffffu, v, 16);
            v += __shfl_xor_sync(0xffffffffu, v, 8);
            v += __shfl_xor_sync(0xffffffffu, v, 4);
            v += __shfl_xor_sync(0xffffffffu, v, 2);
            v += __shfl_xor_sync(0xffffffffu, v, 1);
            if (lane == j) res = v;
        }
        if (lane < 16) g_h1[(nbase + c) * HID + lane] = res;
    }
}

// ---------------- CSR gather aggregation (both layers) ----------------------
// 4 lanes per node; lane c owns float4 chunk c. Self-loop folded into init.
// LAYER==1: out = relu(dinv[n]*sum + b1) -> g_h2 ; LAYER==2: out = dinv[n]*sum -> g_h1
template <int LAYER>
__global__ __launch_bounds__(256) void k_agg(const float* __restrict__ bias) {
    int t = blockIdx.x * blockDim.x + threadIdx.x;
    int n = t >> 2, c = t & 3;
    if (n >= N_NODES) return;

    const float4* H = (const float4*)(LAYER == 1 ? g_h1 : g_h2);
    float dn = g_dinv[n];

    float4 sv = __ldg(&H[n * 4 + c]);                       // self contribution
    float4 acc = make_float4(dn * sv.x, dn * sv.y, dn * sv.z, dn * sv.w);

    int j = g_row[n], je = g_row[n + 1];
    for (; j + 4 <= je; j += 4) {
        int2 e0 = g_edge[j], e1 = g_edge[j + 1], e2 = g_edge[j + 2], e3 = g_edge[j + 3];
        float4 v0 = __ldg(&H[e0.x * 4 + c]);
        float4 v1 = __ldg(&H[e1.x * 4 + c]);
        float4 v2 = __ldg(&H[e2.x * 4 + c]);
        float4 v3 = __ldg(&H[e3.x * 4 + c]);
        float d0 = __int_as_float(e0.y), d1 = __int_as_float(e1.y);
        float d2 = __int_as_float(e2.y), d3 = __int_as_float(e3.y);
        acc.x += d0 * v0.x; acc.y += d0 * v0.y; acc.z += d0 * v0.z; acc.w += d0 * v0.w;
        acc.x += d1 * v1.x; acc.y += d1 * v1.y; acc.z += d1 * v1.z; acc.w += d1 * v1.w;
        acc.x += d2 * v2.x; acc.y += d2 * v2.y; acc.z += d2 * v2.z; acc.w += d2 * v2.w;
        acc.x += d3 * v3.x; acc.y += d3 * v3.y; acc.z += d3 * v3.z; acc.w += d3 * v3.w;
    }
    for (; j < je; j++) {
        int2 e = g_edge[j];
        float4 v = __ldg(&H[e.x * 4 + c]);
        float dd = __int_as_float(e.y);
        acc.x += dd * v.x; acc.y += dd * v.y; acc.z += dd * v.z; acc.w += dd * v.w;
    }

    acc.x *= dn; acc.y *= dn; acc.z *= dn; acc.w *= dn;

    if (LAYER == 1) {
        float4 b = __ldg((const float4*)bias + c);
        acc.x = fmaxf(acc.x + b.x, 0.0f);
        acc.y = fmaxf(acc.y + b.y, 0.0f);
        acc.z = fmaxf(acc.z + b.z, 0.0f);
        acc.w = fmaxf(acc.w + b.w, 0.0f);
        ((float4*)g_h2)[n * 4 + c] = acc;
    } else {
        ((float4*)g_h1)[n * 4 + c] = acc;
    }
}

// ---------------- final: g_h1(agg2) @ W2 + b2 -> log_softmax ----------------
__global__ __launch_bounds__(256) void k_final(const float* __restrict__ W2,
                                               const float* __restrict__ b2,
                                               float* __restrict__ out) {
    __shared__ float W2s[HID * N_CLS];
    __shared__ float b2s[N_CLS];
    for (int i = threadIdx.x; i < HID * N_CLS; i += blockDim.x) W2s[i] = W2[i];
    for (int i = threadIdx.x; i < N_CLS; i += blockDim.x) b2s[i] = b2[i];
    __syncthreads();

    int gw   = (blockIdx.x * blockDim.x + threadIdx.x) >> 5;
    int lane = threadIdx.x & 31;
    if (gw >= N_NODES) return;
    int n = gw;

    float tj = (lane < HID) ? g_h1[n * HID + lane] : 0.0f;

    float z0 = b2s[lane], z1 = b2s[lane + 32];
#pragma unroll
    for (int j = 0; j < HID; j++) {
        float t = __shfl_sync(0xffffffffu, tj, j);
        z0 += t * W2s[j * N_CLS + lane];
        z1 += t * W2s[j * N_CLS + lane + 32];
    }

    float m = fmaxf(z0, z1);
#pragma unroll
    for (int off = 16; off > 0; off >>= 1)
        m = fmaxf(m, __shfl_xor_sync(0xffffffffu, m, off));
    float s = __expf(z0 - m) + __expf(z1 - m);
#pragma unroll
    for (int off = 16; off > 0; off >>= 1)
        s += __shfl_xor_sync(0xffffffffu, s, off);
    float l = m + __logf(s);

    out[n * N_CLS + lane]      = z0 - l;
    out[n * N_CLS + lane + 32] = z1 - l;
}

// ---------------- launch ----------------------------------------------------
extern "C" void kernel_launch(void* const* d_in, const int* in_sizes, int n_in,
                              void* d_out, int out_size) {
    const float* x    = (const float*)d_in[0];
    const void*  eidx = d_in[1];
    const float* W1   = (const float*)d_in[2];
    const float* b1   = (const float*)d_in[3];
    const float* W2   = (const float*)d_in[4];
    const float* b2   = (const float*)d_in[5];
    float* out = (float*)d_out;

    int E = in_sizes[1] / 2;
    if (E > N_EDGES) E = N_EDGES;

    const int T = 256;
    int nb_edges = (E + T - 1) / T;

    k_init<<<NB_N, T>>>((const unsigned*)eidx);
    k_prep<<<nb_edges, T>>>(eidx, E);
    k_scan1<<<NB_N, T>>>();
    k_scan2<<<1, 512>>>();
    k_scan3<<<NB_N, T>>>();
    k_fill<<<nb_edges, T>>>(E);

    k_gemm1<<<N_NODES / 32, T>>>(x, W1);

    k_agg<1><<<(N_NODES * 4 + T - 1) / T, T>>>(b1);
    k_agg<2><<<(N_NODES * 4 + T - 1) / T, T>>>(nullptr);

    k_final<<<(N_NODES * 32 + T - 1) / T, T>>>(W2, b2, out);
}

// round 6
// speedup vs baseline: 1.3275x; 1.0403x over previous
#include <cuda_runtime.h>

#define N_NODES 100000
#define N_EDGES 3200000
#define N_FEAT  512
#define HID     16
#define N_CLS   64
#define NB_N    391              // ceil(N_NODES/256)

// ---------------- scratch (device globals) ---------------------------------
__device__ float g_h1[N_NODES * HID];    // dinv-scaled x@W1 ; later final 16-dim input
__device__ float g_h2[N_NODES * HID];    // dinv-scaled layer-1 output
__device__ float g_dinv[N_NODES];
__device__ int   g_cnt[N_NODES];         // in-degree histogram (excl self-loop)
__device__ int   g_row[N_NODES + 1];     // CSR row offsets
__device__ int   g_cursor[N_NODES];
__device__ int   g_edge[N_EDGES];        // src only, dst-sorted
__device__ int   g_bsum[NB_N];
__device__ int   g_boff[NB_N];
__device__ int   g_is64;

// ---------------- init: zero histogram + detect int64 vs int32 -------------
__global__ void k_init(const unsigned* __restrict__ words) {
    int i = blockIdx.x * blockDim.x + threadIdx.x;
    if (i < N_NODES) g_cnt[i] = 0;
    if (blockIdx.x == 0) {
        unsigned any = 0;
        for (int k = threadIdx.x; k < 4096; k += blockDim.x) any |= words[2 * k + 1];
        int r = __syncthreads_or((int)(any != 0));
        if (threadIdx.x == 0) g_is64 = (r == 0);   // all-high-words zero => int64
    }
}

// ---------------- degree histogram (reads dst half only) --------------------
__global__ void k_hist(const void* __restrict__ eidx, int E) {
    int e = blockIdx.x * blockDim.x + threadIdx.x;
    if (e >= E) return;
    int d;
    if (g_is64) d = (int)((const long long*)eidx)[E + e];
    else        d = ((const int*)eidx)[E + e];
    atomicAdd(&g_cnt[d], 1);
}

// ---------------- scan stage 1: per-block sums ------------------------------
__global__ void k_scan1() {
    int i = blockIdx.x * blockDim.x + threadIdx.x;
    int v = (i < N_NODES) ? g_cnt[i] : 0;
#pragma unroll
    for (int o = 16; o > 0; o >>= 1) v += __shfl_down_sync(0xffffffffu, v, o);
    __shared__ int ws[8];
    if ((threadIdx.x & 31) == 0) ws[threadIdx.x >> 5] = v;
    __syncthreads();
    if (threadIdx.x == 0) {
        int s = 0;
#pragma unroll
        for (int k = 0; k < 8; k++) s += ws[k];
        g_bsum[blockIdx.x] = s;
    }
}

// ---------------- scan stage 2: exclusive scan of block sums ----------------
__global__ void k_scan2() {
    __shared__ int sm[512];
    int t = threadIdx.x;
    int v = (t < NB_N) ? g_bsum[t] : 0;
    sm[t] = v;
    __syncthreads();
#pragma unroll
    for (int o = 1; o < 512; o <<= 1) {
        int y = (t >= o) ? sm[t - o] : 0;
        __syncthreads();
        sm[t] += y;
        __syncthreads();
    }
    if (t < NB_N) g_boff[t] = sm[t] - v;   // exclusive
}

// ---------------- scan stage 3: row offsets, cursors, dinv ------------------
__global__ void k_scan3() {
    int i = blockIdx.x * blockDim.x + threadIdx.x;
    int lane = threadIdx.x & 31, warp = threadIdx.x >> 5;
    int v = (i < N_NODES) ? g_cnt[i] : 0;
    int x = v;
#pragma unroll
    for (int o = 1; o < 32; o <<= 1) {
        int y = __shfl_up_sync(0xffffffffu, x, o);
        if (lane >= o) x += y;
    }
    __shared__ int ws[8];
    if (lane == 31) ws[warp] = x;
    __syncthreads();
    if (threadIdx.x == 0) {
        int s = 0;
#pragma unroll
        for (int k = 0; k < 8; k++) { int t = ws[k]; ws[k] = s; s += t; }
    }
    __syncthreads();
    int excl = x - v + ws[warp] + g_boff[blockIdx.x];
    if (i < N_NODES) {
        g_row[i]    = excl;
        g_cursor[i] = excl;
        g_dinv[i]   = rsqrtf((float)v + 1.0f);     // +1: self-loop
        if (i == N_NODES - 1) g_row[N_NODES] = excl + v;
    }
}

// ---------------- fill CSR: dst-sorted src index -----------------------------
__global__ void k_fill(const void* __restrict__ eidx, int E) {
    int e = blockIdx.x * blockDim.x + threadIdx.x;
    if (e >= E) return;
    int s, d;
    if (g_is64) {
        const long long* p = (const long long*)eidx;
        s = (int)p[e]; d = (int)p[E + e];
    } else {
        const int* p = (const int*)eidx;
        s = p[e]; d = p[E + e];
    }
    int pos = atomicAdd(&g_cursor[d], 1);
    g_edge[pos] = s;
}

// ---------------- GEMM1: g_h1 = dinv * (x @ W1), packed f32x2 FMA -----------
__global__ __launch_bounds__(256) void k_gemm1(const float* __restrict__ x,
                                               const float* __restrict__ W1) {
    __shared__ float2 Ws2[8 * N_FEAT];   // Ws2[j2*512 + k] = (W1[k][2j2], W1[k][2j2+1])
    for (int idx = threadIdx.x; idx < 8 * N_FEAT; idx += blockDim.x) {
        int j2 = idx & 7, k = idx >> 3;
        Ws2[j2 * N_FEAT + k] = make_float2(W1[k * HID + 2 * j2], W1[k * HID + 2 * j2 + 1]);
    }
    __syncthreads();

    int lane  = threadIdx.x & 31;
    int warp  = threadIdx.x >> 5;
    int nbase = blockIdx.x * 32 + warp * 4;

    unsigned long long acc[4][8];
#pragma unroll
    for (int c = 0; c < 4; c++)
#pragma unroll
        for (int j = 0; j < 8; j++) acc[c][j] = 0ull;

    const float* xb = x + (size_t)nbase * N_FEAT;
    const unsigned long long* Wsu = (const unsigned long long*)Ws2;

#pragma unroll 2
    for (int k0 = 0; k0 < N_FEAT; k0 += 32) {
        int k = k0 + lane;
        float xv[4];
        xv[0] = xb[k];
        xv[1] = xb[N_FEAT + k];
        xv[2] = xb[2 * N_FEAT + k];
        xv[3] = xb[3 * N_FEAT + k];
        unsigned long long xx[4];
#pragma unroll
        for (int c = 0; c < 4; c++)
            asm("mov.b64 %0, {%1, %1};" : "=l"(xx[c]) : "f"(xv[c]));
#pragma unroll
        for (int j2 = 0; j2 < 8; j2++) {
            unsigned long long w = Wsu[j2 * N_FEAT + k];
#pragma unroll
            for (int c = 0; c < 4; c++)
                asm("fma.rn.f32x2 %0, %1, %2, %0;" : "+l"(acc[c][j2]) : "l"(xx[c]), "l"(w));
        }
    }

#pragma unroll
    for (int c = 0; c < 4; c++) {
        float av[16];
#pragma unroll
        for (int j2 = 0; j2 < 8; j2++)
            asm("mov.b64 {%0, %1}, %2;" : "=f"(av[2 * j2]), "=f"(av[2 * j2 + 1]) : "l"(acc[c][j2]));
        float res = 0.0f;
#pragma unroll
        for (int j = 0; j < 16; j++) {
            float v = av[j];
            v += __shfl_xor_sync(0xffffffffu, v, 16);
            v += __shfl_xor_sync(0xffffffffu, v, 8);
            v += __shfl_xor_sync(0xffffffffu, v, 4);
            v += __shfl_xor_sync(0xffffffffu, v, 2);
            v += __shfl_xor_sync(0xffffffffu, v, 1);
            if (lane == j) res = v;
        }
        if (lane < 16) g_h1[(nbase + c) * HID + lane] = res * g_dinv[nbase + c];
    }
}

// ---------------- CSR gather aggregation (both layers) ----------------------
// 4 lanes per node; lane c owns float4 chunk c. Records hold src only; features
// are pre-scaled by dinv[src], so sum is unweighted. Self folded into init.
// LAYER==1: g_h2 = dinv * relu(dinv*sum + b1)   LAYER==2: g_h1 = dinv * sum
template <int LAYER>
__global__ __launch_bounds__(256) void k_agg(const float* __restrict__ bias) {
    int t = blockIdx.x * blockDim.x + threadIdx.x;
    int n = t >> 2, c = t & 3;
    if (n >= N_NODES) return;

    const float4* H = (const float4*)(LAYER == 1 ? g_h1 : g_h2);
    float dn = g_dinv[n];

    float4 acc = __ldg(&H[n * 4 + c]);                      // self (already scaled)

    int j = g_row[n], je = g_row[n + 1];
    // MLP-8 main loop: 8 independent record loads, then 8 independent gathers
    for (; j + 8 <= je; j += 8) {
        int s[8];
#pragma unroll
        for (int u = 0; u < 8; u++) s[u] = g_edge[j + u];
        float4 v[8];
#pragma unroll
        for (int u = 0; u < 8; u++) v[u] = __ldg(&H[s[u] * 4 + c]);
#pragma unroll
        for (int u = 0; u < 8; u++) {
            acc.x += v[u].x; acc.y += v[u].y; acc.z += v[u].z; acc.w += v[u].w;
        }
    }
    for (; j < je; j++) {
        float4 v = __ldg(&H[g_edge[j] * 4 + c]);
        acc.x += v.x; acc.y += v.y; acc.z += v.z; acc.w += v.w;
    }

    if (LAYER == 1) {
        float4 b = __ldg((const float4*)bias + c);
        acc.x = dn * fmaxf(dn * acc.x + b.x, 0.0f);
        acc.y = dn * fmaxf(dn * acc.y + b.y, 0.0f);
        acc.z = dn * fmaxf(dn * acc.z + b.z, 0.0f);
        acc.w = dn * fmaxf(dn * acc.w + b.w, 0.0f);
        ((float4*)g_h2)[n * 4 + c] = acc;
    } else {
        acc.x *= dn; acc.y *= dn; acc.z *= dn; acc.w *= dn;
        ((float4*)g_h1)[n * 4 + c] = acc;
    }
}

// ---------------- final: g_h1(agg2) @ W2 + b2 -> log_softmax ----------------
__global__ __launch_bounds__(256) void k_final(const float* __restrict__ W2,
                                               const float* __restrict__ b2,
                                               float* __restrict__ out) {
    __shared__ float W2s[HID * N_CLS];
    __shared__ float b2s[N_CLS];
    for (int i = threadIdx.x; i < HID * N_CLS; i += blockDim.x) W2s[i] = W2[i];
    for (int i = threadIdx.x; i < N_CLS; i += blockDim.x) b2s[i] = b2[i];
    __syncthreads();

    int gw   = (blockIdx.x * blockDim.x + threadIdx.x) >> 5;
    int lane = threadIdx.x & 31;
    if (gw >= N_NODES) return;
    int n = gw;

    float tj = (lane < HID) ? g_h1[n * HID + lane] : 0.0f;

    float z0 = b2s[lane], z1 = b2s[lane + 32];
#pragma unroll
    for (int j = 0; j < HID; j++) {
        float t = __shfl_sync(0xffffffffu, tj, j);
        z0 += t * W2s[j * N_CLS + lane];
        z1 += t * W2s[j * N_CLS + lane + 32];
    }

    float m = fmaxf(z0, z1);
#pragma unroll
    for (int off = 16; off > 0; off >>= 1)
        m = fmaxf(m, __shfl_xor_sync(0xffffffffu, m, off));
    float s = __expf(z0 - m) + __expf(z1 - m);
#pragma unroll
    for (int off = 16; off > 0; off >>= 1)
        s += __shfl_xor_sync(0xffffffffu, s, off);
    float l = m + __logf(s);

    out[n * N_CLS + lane]      = z0 - l;
    out[n * N_CLS + lane + 32] = z1 - l;
}

// ---------------- launch ----------------------------------------------------
extern "C" void kernel_launch(void* const* d_in, const int* in_sizes, int n_in,
                              void* d_out, int out_size) {
    const float* x    = (const float*)d_in[0];
    const void*  eidx = d_in[1];
    const float* W1   = (const float*)d_in[2];
    const float* b1   = (const float*)d_in[3];
    const float* W2   = (const float*)d_in[4];
    const float* b2   = (const float*)d_in[5];
    float* out = (float*)d_out;

    int E = in_sizes[1] / 2;
    if (E > N_EDGES) E = N_EDGES;

    const int T = 256;
    int nb_edges = (E + T - 1) / T;

    k_init<<<NB_N, T>>>((const unsigned*)eidx);
    k_hist<<<nb_edges, T>>>(eidx, E);
    k_scan1<<<NB_N, T>>>();
    k_scan2<<<1, 512>>>();
    k_scan3<<<NB_N, T>>>();
    k_fill<<<nb_edges, T>>>(eidx, E);

    k_gemm1<<<N_NODES / 32, T>>>(x, W1);

    k_agg<1><<<(N_NODES * 4 + T - 1) / T, T>>>(b1);
    k_agg<2><<<(N_NODES * 4 + T - 1) / T, T>>>(nullptr);

    k_final<<<(N_NODES * 32 + T - 1) / T, T>>>(W2, b2, out);
}